// round 10
// baseline (speedup 1.0000x reference)
#include <cuda_runtime.h>
#include <cuda_fp16.h>
#include <cstdint>

// ---------------- problem constants ----------------
#define NTOT 61440      // B*30 positions/nodes
#define NB   2048
#define NE   491520
#define FCO  72

// ---------------- scratch ----------------
__device__ float g_h[NTOT * 12];
__device__ float g_deg[NTOT];
__device__ __align__(256) float g_acc[NTOT * 12];
__device__ __align__(256) __half g_X1h[(size_t)NTOT * 128];
__device__ __align__(256) __half g_X2h[(size_t)NTOT * 512];
__device__ __align__(256) __half g_X3T[(size_t)NB * 3840];  // [g][c*30+t]
__device__ __align__(256) __half g_fcwH[FCO * 3840];
// pre-laid-out fp16 weights
__device__ __align__(256) __half g_wC0[2 * 64 * 48];
__device__ __align__(256) __half g_wD0[2 * 64 * 16];
__device__ __align__(256) __half g_wC1[8 * 4 * 64 * 96];
__device__ __align__(256) __half g_wD1[8 * 4 * 64 * 32];
__device__ __align__(256) __half g_wC2[2 * 16 * 64 * 96];
__device__ __align__(256) __half g_wD2[2 * 16 * 64 * 32];

// ---------------- PTX helpers ----------------
#define CP16(d, s) asm volatile("cp.async.cg.shared.global [%0], [%1], 16;" :: "r"(d), "l"(s))
#define CP16Z(d, s) asm volatile("cp.async.cg.shared.global [%0], [%1], 16, 0;" :: "r"(d), "l"(s))
#define CP_COMMIT() asm volatile("cp.async.commit_group;" ::: "memory")
#define CP_WAIT1() asm volatile("cp.async.wait_group 1;" ::: "memory")
#define CP_WAIT0() asm volatile("cp.async.wait_group 0;" ::: "memory")
#define LDMX4(r0, r1, r2, r3, a) \
    asm volatile("ldmatrix.sync.aligned.m8n8.x4.shared.b16 {%0,%1,%2,%3}, [%4];" \
        : "=r"(r0), "=r"(r1), "=r"(r2), "=r"(r3) : "r"(a))

__device__ __forceinline__ void mma16(float* d, const uint32_t* a, const uint32_t* b) {
    asm volatile(
        "mma.sync.aligned.m16n8k16.row.col.f32.f16.f16.f32 "
        "{%0,%1,%2,%3}, {%4,%5,%6,%7}, {%8,%9}, {%0,%1,%2,%3};"
        : "+f"(d[0]), "+f"(d[1]), "+f"(d[2]), "+f"(d[3])
        : "r"(a[0]), "r"(a[1]), "r"(a[2]), "r"(a[3]), "r"(b[0]), "r"(b[1]));
}
__device__ __forceinline__ void red4(float* addr, float a, float b, float c, float d) {
    asm volatile("red.global.add.v4.f32 [%0], {%1,%2,%3,%4};"
                 :: "l"(addr), "f"(a), "f"(b), "f"(c), "f"(d) : "memory");
}

// ---------------- edge dtype detect ----------------
__device__ __forceinline__ int detect_is64(const void* ei, int tid) {
    __shared__ int sdet;
    if (tid == 0) sdet = 0;
    __syncthreads();
    if (tid < 64) {
        int v = ((const int*)ei)[2 * tid + 1];
        if (v) atomicOr(&sdet, 1);
    }
    __syncthreads();
    return sdet == 0;
}
__device__ __forceinline__ void load_edge(const void* ei, int e, int is64, int& src, int& dst) {
    if (is64) {
        const long long* p = (const long long*)ei;
        src = (int)p[e]; dst = (int)p[NE + e];
    } else {
        const int* p = (const int*)ei;
        src = p[e]; dst = p[NE + e];
    }
}

// ---------------- mega prep kernel ----------------
__global__ __launch_bounds__(256) void k_linDeg(
    const float* __restrict__ x, const float* __restrict__ w, const void* ei,
    const float* __restrict__ cw0, const float* __restrict__ dw0,
    const float* __restrict__ cw1, const float* __restrict__ dw1,
    const float* __restrict__ cw2, const float* __restrict__ dw2,
    const float* __restrict__ fcw) {
    int tid = threadIdx.x;
    int b = blockIdx.x;
    if (b < 240) {
        __shared__ float sw[144];
        if (tid < 144) sw[tid] = w[tid];
        __syncthreads();
        int n = b * 256 + tid;
        float xv[12];
#pragma unroll
        for (int c = 0; c < 12; c++) xv[c] = x[n * 12 + c];
#pragma unroll
        for (int o = 0; o < 12; o++) {
            float s = 0.f;
#pragma unroll
            for (int c = 0; c < 12; c++) s = fmaf(sw[o * 12 + c], xv[c], s);
            g_h[n * 12 + o] = s;
        }
    } else if (b < 2160) {
        int is64 = detect_is64(ei, tid);
        int e = (b - 240) * 256 + tid;
        int src, dst;
        load_edge(ei, e, is64, src, dst);
        (void)src;
        atomicAdd(&g_deg[dst], 1.0f);
    } else if (b < 2928) {           // conv1 -> g_wC1
        int d = (b - 2160) * 256 + tid;
        int r = d / 96, rem = d - r * 96;
        int mb = r >> 8, ch = (r >> 6) & 3, o = r & 63;
        int tap = rem >> 5, cc = rem & 31;
        g_wC1[d] = __float2half(cw1[((mb * 64 + o) * 128 + ch * 32 + cc) * 3 + tap]);
    } else if (b < 3184) {           // down1 -> g_wD1
        int d = (b - 2928) * 256 + tid;
        int r = d >> 5, cc = d & 31;
        int mb = r >> 8, ch = (r >> 6) & 3, o = r & 63;
        g_wD1[d] = __float2half(dw1[(mb * 64 + o) * 128 + ch * 32 + cc]);
    } else if (b < 3952) {           // conv2 -> g_wC2
        int d = (b - 3184) * 256 + tid;
        int r = d / 96, rem = d - r * 96;
        int mb = r >> 10, ch = (r >> 6) & 15, o = r & 63;
        int tap = rem >> 5, cc = rem & 31;
        g_wC2[d] = __float2half(cw2[((mb * 64 + o) * 512 + ch * 32 + cc) * 3 + tap]);
    } else if (b < 4208) {           // down2 -> g_wD2
        int d = (b - 3952) * 256 + tid;
        int r = d >> 5, cc = d & 31;
        int mb = r >> 10, ch = (r >> 6) & 15, o = r & 63;
        g_wD2[d] = __float2half(dw2[(mb * 64 + o) * 512 + ch * 32 + cc]);
    } else if (b < 4232) {           // conv0 -> g_wC0 (K padded 12->16)
        int d = (b - 4208) * 256 + tid;
        int o2 = d / 48, rem = d - o2 * 48;
        int tap = rem >> 4, cc = rem & 15;
        g_wC0[d] = (cc < 12) ? __float2half(cw0[o2 * 36 + cc * 3 + tap])
                             : __float2half(0.f);
    } else if (b < 4240) {           // down0 -> g_wD0
        int d = (b - 4232) * 256 + tid;
        int o2 = d >> 4, cc = d & 15;
        g_wD0[d] = (cc < 12) ? __float2half(dw0[o2 * 12 + cc]) : __float2half(0.f);
    } else {                         // fc weights -> fp16
        int idx = (b - 4240) * 256 + tid;
        if (idx < FCO * 3840) g_fcwH[idx] = __float2half(fcw[idx]);
    }
}

__global__ __launch_bounds__(256) void k_scatter(const void* ei) {
    int tid = threadIdx.x;
    int is64 = detect_is64(ei, tid);
    int e = blockIdx.x * 256 + tid;
    int src, dst;
    load_edge(ei, e, is64, src, dst);
    float norm = rsqrtf(g_deg[src] + 1.0f) * rsqrtf(g_deg[dst] + 1.0f);
    float4 h0 = *(const float4*)(g_h + src * 12);
    float4 h1 = *(const float4*)(g_h + src * 12 + 4);
    float4 h2 = *(const float4*)(g_h + src * 12 + 8);
    float* ad = &g_acc[dst * 12];
    red4(ad,     norm * h0.x, norm * h0.y, norm * h0.z, norm * h0.w);
    red4(ad + 4, norm * h1.x, norm * h1.y, norm * h1.z, norm * h1.w);
    red4(ad + 8, norm * h2.x, norm * h2.y, norm * h2.z, norm * h2.w);
}

// ---------------- mma TCN block 0: fused gcn_out + conv(12->128,dil=1) ----------------
#define SM0_BYTES (128 * 68 * 4)

__global__ __launch_bounds__(256, 2) void k_tcn0M(
    const __half* __restrict__ wC, const __half* __restrict__ wD,
    const float* __restrict__ cb, const float* __restrict__ db,
    const float* __restrict__ gcnb) {
    extern __shared__ __half sh0[];
    const uint32_t s0 = (uint32_t)__cvta_generic_to_shared(sh0);
    __half* sB = sh0;
    const uint32_t aOff = 3264 * 2;
    const uint32_t dOff = (3264 + 3584) * 2;

    const int tid = threadIdx.x;
    const int wrp = tid >> 5, lane = tid & 31;
    const int lr = lane >> 2, lc = lane & 3;
    const int l8 = lane & 7, s1 = (lane >> 3) & 1, s2 = lane >> 4;
    const int mh = wrp & 1;
    const int nq = wrp >> 1;
    const int mb = blockIdx.x;
    const int m0 = mb * 64;
    const int g0 = blockIdx.y * 4;

    for (int idx = tid; idx < 384; idx += 256) {
        int o = idx / 6, pc = idx - (idx / 6) * 6;
        CP16(s0 + aOff + o * 112 + pc * 16, wC + (size_t)(mb * 64 + o) * 48 + pc * 8);
    }
    if (tid < 128) {
        int o = tid >> 1, pc = tid & 1;
        CP16(s0 + dOff + o * 48 + pc * 16, wD + (size_t)(mb * 64 + o) * 16 + pc * 8);
    }
    CP_COMMIT();

    {
        uint4 z = make_uint4(0, 0, 0, 0);
        for (int idx = tid; idx < 408; idx += 256) ((uint4*)sB)[idx] = z;
    }
    __syncthreads();
    for (int idx = tid; idx < 1440; idx += 256) {
        int gi = idx / 360;
        int r = idx - gi * 360;
        int t = r / 12, c = r - (r / 12) * 12;
        int p = (g0 + gi) * 30 + t;
        float di2 = 1.0f / (g_deg[p] + 1.0f);
        float v = g_acc[p * 12 + c] + di2 * g_h[p * 12 + c] + gcnb[c];
        sB[(gi * 34 + t + 2) * 24 + c] = __float2half(v);
    }
    CP_WAIT0();
    __syncthreads();

    float acc1[2][4][4], acc2[2][4][4];
#pragma unroll
    for (int mt = 0; mt < 2; mt++)
#pragma unroll
        for (int nt = 0; nt < 4; nt++)
#pragma unroll
            for (int r = 0; r < 4; r++) { acc1[mt][nt][r] = 0.f; acc2[mt][nt][r] = 0.f; }

    const uint32_t bRow = s0 + nq * (34 * 48);
#pragma unroll
    for (int tap = 0; tap < 3; tap++) {
        uint32_t bf[4][2];
#pragma unroll
        for (int pr = 0; pr < 2; pr++) {
            uint32_t ba = bRow + (tap + (pr * 2 + s2) * 8 + l8) * 48 + s1 * 16;
            LDMX4(bf[pr * 2][0], bf[pr * 2][1], bf[pr * 2 + 1][0], bf[pr * 2 + 1][1], ba);
        }
        uint32_t af[2][4];
#pragma unroll
        for (int mt = 0; mt < 2; mt++) {
            uint32_t aa = s0 + aOff + (mh * 32 + mt * 16 + s1 * 8 + l8) * 112 +
                          tap * 32 + s2 * 16;
            LDMX4(af[mt][0], af[mt][1], af[mt][2], af[mt][3], aa);
        }
#pragma unroll
        for (int mt = 0; mt < 2; mt++)
#pragma unroll
            for (int nt = 0; nt < 4; nt++)
                mma16(acc1[mt][nt], af[mt], bf[nt]);
        if (tap == 2) {
            uint32_t df[2][4];
#pragma unroll
            for (int mt = 0; mt < 2; mt++) {
                uint32_t da = s0 + dOff + (mh * 32 + mt * 16 + s1 * 8 + l8) * 48 + s2 * 16;
                LDMX4(df[mt][0], df[mt][1], df[mt][2], df[mt][3], da);
            }
#pragma unroll
            for (int mt = 0; mt < 2; mt++)
#pragma unroll
                for (int nt = 0; nt < 4; nt++)
                    mma16(acc2[mt][nt], df[mt], bf[nt]);
        }
    }
    __syncthreads();

    float* sO = (float*)sh0;
#pragma unroll
    for (int mt = 0; mt < 2; mt++) {
        int ob = m0 + mh * 32 + mt * 16 + lr;
        float bc0 = cb[ob], bc1 = cb[ob + 8];
        float bd0 = db[ob], bd1 = db[ob + 8];
#pragma unroll
        for (int nt = 0; nt < 4; nt++) {
#pragma unroll
            for (int r = 0; r < 4; r++) {
                float bc = (r >= 2) ? bc1 : bc0;
                float bd = (r >= 2) ? bd1 : bd0;
                int oo = mh * 32 + mt * 16 + lr + ((r >= 2) ? 8 : 0);
                int po = nq * 32 + nt * 8 + lc * 2 + (r & 1);
                float y = fmaxf(fmaxf(acc1[mt][nt][r] + bc, 0.f) + acc2[mt][nt][r] + bd, 0.f);
                sO[po * 68 + oo] = y;
            }
        }
    }
    __syncthreads();
#pragma unroll
    for (int gi = 0; gi < 4; gi++) {
        for (int idx = tid; idx < 480; idx += 256) {
            int t = idx >> 4, q = idx & 15;
            float4 v = *(float4*)&sO[(gi * 32 + t) * 68 + q * 4];
            __half2 h0 = __floats2half2_rn(v.x, v.y);
            __half2 h1 = __floats2half2_rn(v.z, v.w);
            uint2 u;
            u.x = *(uint32_t*)&h0; u.y = *(uint32_t*)&h1;
            *(uint2*)(g_X1h + (size_t)((g0 + gi) * 30 + t) * 128 + m0 + q * 4) = u;
        }
    }
}

// ---------------- fp16 mma TCN block: 8 graphs/CTA, 2 graphs/warp ----------------
// OUTM: 1 = fp16 [pos][C]; 2 = fp16 transposed [g][c*30+t]
template <int CIN, int COUT, int DIL, int NCH, int OUTM>
__global__ __launch_bounds__(256, 1) void k_tcnH(
    const __half* __restrict__ Xin, const __half* __restrict__ wC,
    const __half* __restrict__ wD, const float* __restrict__ cb,
    const float* __restrict__ db, __half* __restrict__ Xout) {
    constexpr int W = 32 + 2 * DIL;
    constexpr int BB = 8 * W * 40;            // halves per stage: B (8 graphs)
    constexpr int AB = 64 * 104;
    constexpr int DB = 64 * 40;
    constexpr int STG = BB + AB + DB;
    extern __shared__ __half smh[];
    const uint32_t smem0 = (uint32_t)__cvta_generic_to_shared(smh);

    const int tid = threadIdx.x;
    const int wrp = tid >> 5, lane = tid & 31;
    const int lr = lane >> 2, lc = lane & 3;
    const int l8 = lane & 7, s1 = (lane >> 3) & 1, s2 = lane >> 4;
    const int mh = wrp & 1;
    const int nq = wrp >> 1;            // 0..3; warp handles graphs nq and nq+4
    const int mb = blockIdx.x;
    const int m0 = mb * 64;
    const int g0 = blockIdx.y * 8;

    // zero halo rows of all 3 stages (8 graphs each)
    {
        constexpr int ZR = 2 * DIL + 2;
        uint4 z = make_uint4(0, 0, 0, 0);
        for (int idx = tid; idx < 3 * 8 * ZR * 5; idx += 256) {
            int bufg = idx / (ZR * 5);
            int r = idx - bufg * (ZR * 5);
            int zr = r / 5, pc = r - (r / 5) * 5;
            int u = (zr < 2 * DIL) ? zr : (30 + zr);
            int buf = bufg >> 3, gi = bufg & 7;
            *(uint4*)(smh + buf * STG + (gi * W + u) * 40 + pc * 8) = z;
        }
    }

    auto stage = [&](int chk, int buf) {
        uint32_t sb = smem0 + buf * (STG * 2);
        for (int idx = tid; idx < 960; idx += 256) {
            int gi = idx / 120;
            int r = idx - gi * 120;
            int t = r >> 2, pc = r & 3;
            uint32_t dst = sb + (gi * W + t + 2 * DIL) * 80 + pc * 16;
            const __half* src = Xin + ((size_t)(g0 + gi) * 30 + t) * CIN + chk * 32 + pc * 8;
            CP16(dst, src);
        }
        uint32_t aD = sb + BB * 2;
        const __half* srcA = wC + ((size_t)(mb * NCH + chk) * 64) * 96;
        for (int idx = tid; idx < 768; idx += 256) {
            int o = idx / 12, pc = idx - (idx / 12) * 12;
            CP16(aD + o * 208 + pc * 16, srcA + o * 96 + pc * 8);
        }
        uint32_t dD = sb + (BB + AB) * 2;
        const __half* srcD = wD + ((size_t)(mb * NCH + chk) * 64) * 32;
        {
            int o = tid >> 2, pc = tid & 3;
            CP16(dD + o * 80 + pc * 16, srcD + o * 32 + pc * 8);
        }
        CP_COMMIT();
    };

    float acc1[2][2][4][4], acc2[2][2][4][4];   // [mt][gsel][nt][r]
#pragma unroll
    for (int mt = 0; mt < 2; mt++)
#pragma unroll
        for (int gs = 0; gs < 2; gs++)
#pragma unroll
            for (int nt = 0; nt < 4; nt++)
#pragma unroll
                for (int r = 0; r < 4; r++) { acc1[mt][gs][nt][r] = 0.f; acc2[mt][gs][nt][r] = 0.f; }

    stage(0, 0);
    stage(1, 1);

    for (int chk = 0; chk < NCH; chk++) {
        const int buf = chk % 3;
        if (chk + 1 < NCH) { CP_WAIT1(); } else { CP_WAIT0(); }
        __syncthreads();
        if (chk + 2 < NCH) stage(chk + 2, (chk + 2) % 3);

        const uint32_t sb = smem0 + buf * (STG * 2);
        const uint32_t aB = sb + BB * 2;
        const uint32_t dB = sb + (BB + AB) * 2;

#pragma unroll
        for (int kh = 0; kh < 2; kh++) {
            const uint32_t kb = kh * 32;
#pragma unroll
            for (int tap = 0; tap < 3; tap++) {
                uint32_t bf[2][4][2];
#pragma unroll
                for (int gs = 0; gs < 2; gs++) {
                    uint32_t bRow = sb + (nq + gs * 4) * (W * 80);
#pragma unroll
                    for (int pr = 0; pr < 2; pr++) {
                        uint32_t ba = bRow +
                            (tap * DIL + (pr * 2 + s2) * 8 + l8) * 80 + kb + s1 * 16;
                        LDMX4(bf[gs][pr * 2][0], bf[gs][pr * 2][1],
                              bf[gs][pr * 2 + 1][0], bf[gs][pr * 2 + 1][1], ba);
                    }
                }
                uint32_t af[2][4];
#pragma unroll
                for (int mt = 0; mt < 2; mt++) {
                    uint32_t aa = aB + (mh * 32 + mt * 16 + s1 * 8 + l8) * 208 +
                                  tap * 64 + kb + s2 * 16;
                    LDMX4(af[mt][0], af[mt][1], af[mt][2], af[mt][3], aa);
                }
#pragma unroll
                for (int mt = 0; mt < 2; mt++)
#pragma unroll
                    for (int gs = 0; gs < 2; gs++)
#pragma unroll
                        for (int nt = 0; nt < 4; nt++)
                            mma16(acc1[mt][gs][nt], af[mt], bf[gs][nt]);
                if (tap == 2) {
                    uint32_t df[2][4];
#pragma unroll
                    for (int mt = 0; mt < 2; mt++) {
                        uint32_t da = dB + (mh * 32 + mt * 16 + s1 * 8 + l8) * 80 +
                                      kb + s2 * 16;
                        LDMX4(df[mt][0], df[mt][1], df[mt][2], df[mt][3], da);
                    }
#pragma unroll
                    for (int mt = 0; mt < 2; mt++)
#pragma unroll
                        for (int gs = 0; gs < 2; gs++)
#pragma unroll
                            for (int nt = 0; nt < 4; nt++)
                                mma16(acc2[mt][gs][nt], df[mt], bf[gs][nt]);
                }
            }
        }
    }
    __syncthreads();   // all warps done before epilogue overwrites staging smem

    float* sO = (float*)smh;   // [256 padded pos][68]
#pragma unroll
    for (int mt = 0; mt < 2; mt++) {
        int ob = m0 + mh * 32 + mt * 16 + lr;
        float bc0 = cb[ob], bc1 = cb[ob + 8];
        float bd0 = db[ob], bd1 = db[ob + 8];
#pragma unroll
        for (int gs = 0; gs < 2; gs++) {
#pragma unroll
            for (int nt = 0; nt < 4; nt++) {
#pragma unroll
                for (int r = 0; r < 4; r++) {
                    float bc = (r >= 2) ? bc1 : bc0;
                    float bd = (r >= 2) ? bd1 : bd0;
                    int oo = mh * 32 + mt * 16 + lr + ((r >= 2) ? 8 : 0);
                    int po = (nq + gs * 4) * 32 + nt * 8 + lc * 2 + (r & 1);
                    float y = fmaxf(fmaxf(acc1[mt][gs][nt][r] + bc, 0.f) +
                                    acc2[mt][gs][nt][r] + bd, 0.f);
                    sO[po * 68 + oo] = y;
                }
            }
        }
    }
    __syncthreads();
    if (OUTM == 1) {
#pragma unroll
        for (int gi = 0; gi < 8; gi++) {
            for (int idx = tid; idx < 480; idx += 256) {
                int t = idx >> 4, q = idx & 15;
                float4 v = *(float4*)&sO[(gi * 32 + t) * 68 + q * 4];
                __half2 h0 = __floats2half2_rn(v.x, v.y);
                __half2 h1 = __floats2half2_rn(v.z, v.w);
                uint2 u;
                u.x = *(uint32_t*)&h0; u.y = *(uint32_t*)&h1;
                *(uint2*)(Xout + (size_t)((g0 + gi) * 30 + t) * COUT + m0 + q * 4) = u;
            }
        }
    } else {
#pragma unroll
        for (int gi = 0; gi < 8; gi++) {
            for (int idx = tid; idx < 960; idx += 256) {
                int c = idx / 15, th = idx - (idx / 15) * 15;
                int t = th * 2;
                float a = sO[(gi * 32 + t) * 68 + c];
                float b = sO[(gi * 32 + t + 1) * 68 + c];
                __half2 h = __floats2half2_rn(a, b);
                *(__half2*)(Xout + (size_t)(g0 + gi) * 3840 + (m0 + c) * 30 + t) = h;
            }
        }
    }
}

// ---------------- tensor-core FC: GF=32 graphs per CTA ----------------
#define FC_XST 40
#define FC_XBUF (32 * 40)
#define FC_WBUF (80 * 40)
#define FC_STRIDE (8 * FC_XBUF + 8 * FC_WBUF)
#define FC_SMEM (2 * FC_STRIDE * 2)

__global__ __launch_bounds__(256, 1) void k_fcM(
    const __half* __restrict__ X3T, const __half* __restrict__ fcwH,
    const float* __restrict__ fcb, float* __restrict__ out) {
    extern __shared__ __half sh[];
    const uint32_t s0 = (uint32_t)__cvta_generic_to_shared(sh);
    const int tid = threadIdx.x;
    const int wrp = tid >> 5, lane = tid & 31;
    const int l8 = lane & 7, s1 = (lane >> 3) & 1, s2 = lane >> 4;
    const int lr = lane >> 2, lc = lane & 3;
    const int g0 = blockIdx.x * 32;
    const int ks = wrp;

    auto stage = [&](int ch, int buf) {
        uint32_t base = s0 + buf * (FC_STRIDE * 2);
        for (int i = tid; i < 1024; i += 256) {
            int kss = i >> 7, r = i & 127;
            int g = r >> 2, q = r & 3;
            uint32_t dst = base + (kss * FC_XBUF + g * FC_XST) * 2 + q * 16;
            const __half* src = X3T + (size_t)(g0 + g) * 3840 + kss * 480 + ch * 32 + q * 8;
            CP16(dst, src);
        }
        for (int i = tid; i < 2560; i += 256) {
            int kss = i / 320, r = i - kss * 320;
            int j = r >> 2, q = r & 3;
            uint32_t dst = base + (8 * FC_XBUF + kss * FC_WBUF + j * FC_XST) * 2 + q * 16;
            const __half* src = fcwH + (size_t)(j < FCO ? j : 0) * 3840 + kss * 480 + ch * 32 + q * 8;
            if (j < FCO) CP16(dst, src); else CP16Z(dst, src);
        }
        CP_COMMIT();
    };

    float acc[2][10][4];
#pragma unroll
    for (int mt = 0; mt < 2; mt++)
#pragma unroll
        for (int nt = 0; nt < 10; nt++)
#pragma unroll
            for (int r = 0; r < 4; r++) acc[mt][nt][r] = 0.f;

    stage(0, 0);
    stage(1, 1);

    for (int ch = 0; ch < 15; ch++) {
        int buf = ch & 1;
        if (ch + 1 < 15) { CP_WAIT1(); } else { CP_WAIT0(); }
        __syncthreads();
        uint32_t xB = s0 + buf * (FC_STRIDE * 2) + ks * (FC_XBUF * 2);
        uint32_t wB = s0 + buf * (FC_STRIDE * 2) + (8 * FC_XBUF + ks * FC_WBUF) * 2;
#pragma unroll
        for (int k16 = 0; k16 < 2; k16++) {
            uint32_t kb = k16 * 32;
            uint32_t af[2][4];
#pragma unroll
            for (int mt = 0; mt < 2; mt++)
                LDMX4(af[mt][0], af[mt][1], af[mt][2], af[mt][3],
                      xB + (mt * 16 + s1 * 8 + l8) * 80 + kb + s2 * 16);
            uint32_t bf[10][2];
#pragma unroll
            for (int jt = 0; jt < 5; jt++) {
                LDMX4(bf[jt * 2][0], bf[jt * 2][1], bf[jt * 2 + 1][0], bf[jt * 2 + 1][1],
                      wB + (jt * 16 + s2 * 8 + l8) * 80 + kb + s1 * 16);
            }
#pragma unroll
            for (int mt = 0; mt < 2; mt++)
#pragma unroll
                for (int nt = 0; nt < 10; nt++) mma16(acc[mt][nt], af[mt], bf[nt]);
        }
        __syncthreads();
        if (ch + 2 < 15) stage(ch + 2, buf);
    }

    __syncthreads();
    float* sred = (float*)sh;   // [8][32][80]
#pragma unroll
    for (int mt = 0; mt < 2; mt++)
#pragma unroll
        for (int nt = 0; nt < 10; nt++)
#pragma unroll
            for (int r = 0; r < 4; r++) {
                int g = mt * 16 + lr + ((r & 2) ? 8 : 0);
                int j = nt * 8 + lc * 2 + (r & 1);
                sred[(ks * 32 + g) * 80 + j] = acc[mt][nt][r];
            }
    __syncthreads();
    for (int idx = tid; idx < 32 * FCO; idx += 256) {
        int g = idx / FCO, j = idx - (idx / FCO) * FCO;
        float s = 0.f;
#pragma unroll
        for (int w2 = 0; w2 < 8; w2++) s += sred[(w2 * 32 + g) * 80 + j];
        out[(size_t)(g0 + g) * FCO + j] = s + fcb[j];
    }
}

// ---------------- launch ----------------
extern "C" void kernel_launch(void* const* d_in, const int* in_sizes, int n_in,
                              void* d_out, int out_size) {
    const float* x    = (const float*)d_in[0];
    const void*  ei   = d_in[1];
    const float* gcnw = (const float*)d_in[2];
    const float* gcnb = (const float*)d_in[3];
    const float* cw0  = (const float*)d_in[4];
    const float* cb0  = (const float*)d_in[5];
    const float* dw0  = (const float*)d_in[6];
    const float* db0  = (const float*)d_in[7];
    const float* cw1  = (const float*)d_in[8];
    const float* cb1  = (const float*)d_in[9];
    const float* dw1  = (const float*)d_in[10];
    const float* db1  = (const float*)d_in[11];
    const float* cw2  = (const float*)d_in[12];
    const float* cb2  = (const float*)d_in[13];
    const float* dw2  = (const float*)d_in[14];
    const float* db2  = (const float*)d_in[15];
    const float* fcw  = (const float*)d_in[16];
    const float* fcb  = (const float*)d_in[17];
    float* out = (float*)d_out;

    void *pX1h, *pX2h, *pX3T, *pDeg, *pAcc;
    void *pWC0, *pWD0, *pWC1, *pWD1, *pWC2, *pWD2, *pFcwH;
    cudaGetSymbolAddress(&pX1h, g_X1h);
    cudaGetSymbolAddress(&pX2h, g_X2h);
    cudaGetSymbolAddress(&pX3T, g_X3T);
    cudaGetSymbolAddress(&pDeg, g_deg);
    cudaGetSymbolAddress(&pAcc, g_acc);
    cudaGetSymbolAddress(&pWC0, g_wC0);
    cudaGetSymbolAddress(&pWD0, g_wD0);
    cudaGetSymbolAddress(&pWC1, g_wC1);
    cudaGetSymbolAddress(&pWD1, g_wD1);
    cudaGetSymbolAddress(&pWC2, g_wC2);
    cudaGetSymbolAddress(&pWD2, g_wD2);
    cudaGetSymbolAddress(&pFcwH, g_fcwH);

    cudaMemsetAsync(pDeg, 0, NTOT * sizeof(float));
    cudaMemsetAsync(pAcc, 0, NTOT * 12 * sizeof(float));

    k_linDeg<<<5320, 256>>>(x, gcnw, ei, cw0, dw0, cw1, dw1, cw2, dw2, fcw);
    k_scatter<<<NE / 256, 256>>>(ei);

    cudaFuncSetAttribute(k_tcn0M, cudaFuncAttributeMaxDynamicSharedMemorySize, SM0_BYTES);
    k_tcn0M<<<dim3(2, NB / 4), 256, SM0_BYTES>>>(
        (const __half*)pWC0, (const __half*)pWD0, cb0, db0, gcnb);

    constexpr int SM1 = 3 * (8 * 38 * 40 + 64 * 104 + 64 * 40) * 2;
    constexpr int SM2 = 3 * (8 * 50 * 40 + 64 * 104 + 64 * 40) * 2;
    cudaFuncSetAttribute((const void*)k_tcnH<128, 512, 3, 4, 1>,
                         cudaFuncAttributeMaxDynamicSharedMemorySize, SM1);
    cudaFuncSetAttribute((const void*)k_tcnH<512, 128, 9, 16, 2>,
                         cudaFuncAttributeMaxDynamicSharedMemorySize, SM2);
    k_tcnH<128, 512, 3, 4, 1><<<dim3(8, NB / 8), 256, SM1>>>(
        (const __half*)pX1h, (const __half*)pWC1, (const __half*)pWD1, cb1, db1,
        (__half*)pX2h);
    k_tcnH<512, 128, 9, 16, 2><<<dim3(2, NB / 8), 256, SM2>>>(
        (const __half*)pX2h, (const __half*)pWC2, (const __half*)pWD2, cb2, db2,
        (__half*)pX3T);

    cudaFuncSetAttribute(k_fcM, cudaFuncAttributeMaxDynamicSharedMemorySize, FC_SMEM);
    k_fcM<<<NB / 32, 256, FC_SMEM>>>((const __half*)pX3T, (const __half*)pFcwH, fcb, out);
}

// round 11
// speedup vs baseline: 1.1398x; 1.1398x over previous
#include <cuda_runtime.h>
#include <cuda_fp16.h>
#include <cstdint>

// ---------------- problem constants ----------------
#define NTOT 61440      // B*30 positions/nodes
#define NB   2048
#define NE   491520
#define FCO  72

// ---------------- scratch ----------------
__device__ float g_h[NTOT * 12];
__device__ float g_deg[NTOT];
__device__ __align__(256) float g_acc[NTOT * 12];
__device__ __align__(256) __half g_X1h[(size_t)NTOT * 128];
__device__ __align__(256) __half g_X2h[(size_t)NTOT * 512];
__device__ __align__(256) __half g_X3T[(size_t)NB * 3840];  // [g][c*30+t]
__device__ __align__(256) __half g_fcwH[FCO * 3840];
// pre-laid-out fp16 weights
__device__ __align__(256) __half g_wC0[2 * 64 * 48];
__device__ __align__(256) __half g_wD0[2 * 64 * 16];
__device__ __align__(256) __half g_wC1[8 * 4 * 64 * 96];
__device__ __align__(256) __half g_wD1[8 * 4 * 64 * 32];
__device__ __align__(256) __half g_wC2[2 * 16 * 64 * 96];
__device__ __align__(256) __half g_wD2[2 * 16 * 64 * 32];

// ---------------- PTX helpers ----------------
#define CP16(d, s) asm volatile("cp.async.cg.shared.global [%0], [%1], 16;" :: "r"(d), "l"(s))
#define CP16Z(d, s) asm volatile("cp.async.cg.shared.global [%0], [%1], 16, 0;" :: "r"(d), "l"(s))
#define CP_COMMIT() asm volatile("cp.async.commit_group;" ::: "memory")
#define CP_WAIT1() asm volatile("cp.async.wait_group 1;" ::: "memory")
#define CP_WAIT0() asm volatile("cp.async.wait_group 0;" ::: "memory")
#define LDMX4(r0, r1, r2, r3, a) \
    asm volatile("ldmatrix.sync.aligned.m8n8.x4.shared.b16 {%0,%1,%2,%3}, [%4];" \
        : "=r"(r0), "=r"(r1), "=r"(r2), "=r"(r3) : "r"(a))

__device__ __forceinline__ void mma16(float* d, const uint32_t* a, const uint32_t* b) {
    asm volatile(
        "mma.sync.aligned.m16n8k16.row.col.f32.f16.f16.f32 "
        "{%0,%1,%2,%3}, {%4,%5,%6,%7}, {%8,%9}, {%0,%1,%2,%3};"
        : "+f"(d[0]), "+f"(d[1]), "+f"(d[2]), "+f"(d[3])
        : "r"(a[0]), "r"(a[1]), "r"(a[2]), "r"(a[3]), "r"(b[0]), "r"(b[1]));
}
__device__ __forceinline__ void red4(float* addr, float a, float b, float c, float d) {
    asm volatile("red.global.add.v4.f32 [%0], {%1,%2,%3,%4};"
                 :: "l"(addr), "f"(a), "f"(b), "f"(c), "f"(d) : "memory");
}

// ---------------- edge dtype detect ----------------
__device__ __forceinline__ int detect_is64(const void* ei, int tid) {
    __shared__ int sdet;
    if (tid == 0) sdet = 0;
    __syncthreads();
    if (tid < 64) {
        int v = ((const int*)ei)[2 * tid + 1];
        if (v) atomicOr(&sdet, 1);
    }
    __syncthreads();
    return sdet == 0;
}
__device__ __forceinline__ void load_edge(const void* ei, int e, int is64, int& src, int& dst) {
    if (is64) {
        const long long* p = (const long long*)ei;
        src = (int)p[e]; dst = (int)p[NE + e];
    } else {
        const int* p = (const int*)ei;
        src = p[e]; dst = p[NE + e];
    }
}

// ---------------- GCN: linear + degree only ----------------
__global__ __launch_bounds__(256) void k_linDeg(
    const float* __restrict__ x, const float* __restrict__ w, const void* ei) {
    int tid = threadIdx.x;
    int b = blockIdx.x;
    if (b < 240) {
        __shared__ float sw[144];
        if (tid < 144) sw[tid] = w[tid];
        __syncthreads();
        int n = b * 256 + tid;
        float xv[12];
#pragma unroll
        for (int c = 0; c < 12; c++) xv[c] = x[n * 12 + c];
#pragma unroll
        for (int o = 0; o < 12; o++) {
            float s = 0.f;
#pragma unroll
            for (int c = 0; c < 12; c++) s = fmaf(sw[o * 12 + c], xv[c], s);
            g_h[n * 12 + o] = s;
        }
    } else {
        int is64 = detect_is64(ei, tid);
        int e = (b - 240) * 256 + tid;
        int src, dst;
        load_edge(ei, e, is64, src, dst);
        (void)src;
        atomicAdd(&g_deg[dst], 1.0f);
    }
}

// ---------------- scatter + (overlapped) weight prep ----------------
__global__ __launch_bounds__(256) void k_scatterW(
    const void* ei,
    const float* __restrict__ cw0, const float* __restrict__ dw0,
    const float* __restrict__ cw1, const float* __restrict__ dw1,
    const float* __restrict__ cw2, const float* __restrict__ dw2,
    const float* __restrict__ fcw) {
    int tid = threadIdx.x;
    int b = blockIdx.x;
    if (b < 1920) {
        int is64 = detect_is64(ei, tid);
        int e = b * 256 + tid;
        int src, dst;
        load_edge(ei, e, is64, src, dst);
        float norm = rsqrtf(g_deg[src] + 1.0f) * rsqrtf(g_deg[dst] + 1.0f);
        float4 h0 = *(const float4*)(g_h + src * 12);
        float4 h1 = *(const float4*)(g_h + src * 12 + 4);
        float4 h2 = *(const float4*)(g_h + src * 12 + 8);
        float* ad = &g_acc[dst * 12];
        red4(ad,     norm * h0.x, norm * h0.y, norm * h0.z, norm * h0.w);
        red4(ad + 4, norm * h1.x, norm * h1.y, norm * h1.z, norm * h1.w);
        red4(ad + 8, norm * h2.x, norm * h2.y, norm * h2.z, norm * h2.w);
        return;
    }
    int b2 = b - 1920;
    if (b2 < 768) {                  // conv1 -> g_wC1
        int d = b2 * 256 + tid;
        int r = d / 96, rem = d - r * 96;
        int mb = r >> 8, ch = (r >> 6) & 3, o = r & 63;
        int tap = rem >> 5, cc = rem & 31;
        g_wC1[d] = __float2half(cw1[((mb * 64 + o) * 128 + ch * 32 + cc) * 3 + tap]);
    } else if (b2 < 1024) {          // down1 -> g_wD1
        int d = (b2 - 768) * 256 + tid;
        int r = d >> 5, cc = d & 31;
        int mb = r >> 8, ch = (r >> 6) & 3, o = r & 63;
        g_wD1[d] = __float2half(dw1[(mb * 64 + o) * 128 + ch * 32 + cc]);
    } else if (b2 < 1792) {          // conv2 -> g_wC2
        int d = (b2 - 1024) * 256 + tid;
        int r = d / 96, rem = d - r * 96;
        int mb = r >> 10, ch = (r >> 6) & 15, o = r & 63;
        int tap = rem >> 5, cc = rem & 31;
        g_wC2[d] = __float2half(cw2[((mb * 64 + o) * 512 + ch * 32 + cc) * 3 + tap]);
    } else if (b2 < 2048) {          // down2 -> g_wD2
        int d = (b2 - 1792) * 256 + tid;
        int r = d >> 5, cc = d & 31;
        int mb = r >> 10, ch = (r >> 6) & 15, o = r & 63;
        g_wD2[d] = __float2half(dw2[(mb * 64 + o) * 512 + ch * 32 + cc]);
    } else if (b2 < 2072) {          // conv0 -> g_wC0 (K padded 12->16)
        int d = (b2 - 2048) * 256 + tid;
        int o2 = d / 48, rem = d - o2 * 48;
        int tap = rem >> 4, cc = rem & 15;
        g_wC0[d] = (cc < 12) ? __float2half(cw0[o2 * 36 + cc * 3 + tap])
                             : __float2half(0.f);
    } else if (b2 < 2080) {          // down0 -> g_wD0
        int d = (b2 - 2072) * 256 + tid;
        int o2 = d >> 4, cc = d & 15;
        g_wD0[d] = (cc < 12) ? __float2half(dw0[o2 * 12 + cc]) : __float2half(0.f);
    } else {                         // fc weights -> fp16
        int idx = (b2 - 2080) * 256 + tid;
        if (idx < FCO * 3840) g_fcwH[idx] = __float2half(fcw[idx]);
    }
}

// ---------------- mma TCN block 0: fused gcn_out + conv(12->128,dil=1) ----------------
#define SM0_BYTES (128 * 68 * 4)

__global__ __launch_bounds__(256, 2) void k_tcn0M(
    const __half* __restrict__ wC, const __half* __restrict__ wD,
    const float* __restrict__ cb, const float* __restrict__ db,
    const float* __restrict__ gcnb) {
    extern __shared__ __half sh0[];
    const uint32_t s0 = (uint32_t)__cvta_generic_to_shared(sh0);
    __half* sB = sh0;
    const uint32_t aOff = 3264 * 2;
    const uint32_t dOff = (3264 + 3584) * 2;

    const int tid = threadIdx.x;
    const int wrp = tid >> 5, lane = tid & 31;
    const int lr = lane >> 2, lc = lane & 3;
    const int l8 = lane & 7, s1 = (lane >> 3) & 1, s2 = lane >> 4;
    const int mh = wrp & 1;
    const int nq = wrp >> 1;
    const int mb = blockIdx.x;
    const int m0 = mb * 64;
    const int g0 = blockIdx.y * 4;

    for (int idx = tid; idx < 384; idx += 256) {
        int o = idx / 6, pc = idx - (idx / 6) * 6;
        CP16(s0 + aOff + o * 112 + pc * 16, wC + (size_t)(mb * 64 + o) * 48 + pc * 8);
    }
    if (tid < 128) {
        int o = tid >> 1, pc = tid & 1;
        CP16(s0 + dOff + o * 48 + pc * 16, wD + (size_t)(mb * 64 + o) * 16 + pc * 8);
    }
    CP_COMMIT();

    {
        uint4 z = make_uint4(0, 0, 0, 0);
        for (int idx = tid; idx < 408; idx += 256) ((uint4*)sB)[idx] = z;
    }
    __syncthreads();
    for (int idx = tid; idx < 1440; idx += 256) {
        int gi = idx / 360;
        int r = idx - gi * 360;
        int t = r / 12, c = r - (r / 12) * 12;
        int p = (g0 + gi) * 30 + t;
        float di2 = 1.0f / (g_deg[p] + 1.0f);
        float v = g_acc[p * 12 + c] + di2 * g_h[p * 12 + c] + gcnb[c];
        sB[(gi * 34 + t + 2) * 24 + c] = __float2half(v);
    }
    CP_WAIT0();
    __syncthreads();

    float acc1[2][4][4], acc2[2][4][4];
#pragma unroll
    for (int mt = 0; mt < 2; mt++)
#pragma unroll
        for (int nt = 0; nt < 4; nt++)
#pragma unroll
            for (int r = 0; r < 4; r++) { acc1[mt][nt][r] = 0.f; acc2[mt][nt][r] = 0.f; }

    const uint32_t bRow = s0 + nq * (34 * 48);
#pragma unroll
    for (int tap = 0; tap < 3; tap++) {
        uint32_t bf[4][2];
#pragma unroll
        for (int pr = 0; pr < 2; pr++) {
            uint32_t ba = bRow + (tap + (pr * 2 + s2) * 8 + l8) * 48 + s1 * 16;
            LDMX4(bf[pr * 2][0], bf[pr * 2][1], bf[pr * 2 + 1][0], bf[pr * 2 + 1][1], ba);
        }
        uint32_t af[2][4];
#pragma unroll
        for (int mt = 0; mt < 2; mt++) {
            uint32_t aa = s0 + aOff + (mh * 32 + mt * 16 + s1 * 8 + l8) * 112 +
                          tap * 32 + s2 * 16;
            LDMX4(af[mt][0], af[mt][1], af[mt][2], af[mt][3], aa);
        }
#pragma unroll
        for (int mt = 0; mt < 2; mt++)
#pragma unroll
            for (int nt = 0; nt < 4; nt++)
                mma16(acc1[mt][nt], af[mt], bf[nt]);
        if (tap == 2) {
            uint32_t df[2][4];
#pragma unroll
            for (int mt = 0; mt < 2; mt++) {
                uint32_t da = s0 + dOff + (mh * 32 + mt * 16 + s1 * 8 + l8) * 48 + s2 * 16;
                LDMX4(df[mt][0], df[mt][1], df[mt][2], df[mt][3], da);
            }
#pragma unroll
            for (int mt = 0; mt < 2; mt++)
#pragma unroll
                for (int nt = 0; nt < 4; nt++)
                    mma16(acc2[mt][nt], df[mt], bf[nt]);
        }
    }
    __syncthreads();

    float* sO = (float*)sh0;
#pragma unroll
    for (int mt = 0; mt < 2; mt++) {
        int ob = m0 + mh * 32 + mt * 16 + lr;
        float bc0 = cb[ob], bc1 = cb[ob + 8];
        float bd0 = db[ob], bd1 = db[ob + 8];
#pragma unroll
        for (int nt = 0; nt < 4; nt++) {
#pragma unroll
            for (int r = 0; r < 4; r++) {
                float bc = (r >= 2) ? bc1 : bc0;
                float bd = (r >= 2) ? bd1 : bd0;
                int oo = mh * 32 + mt * 16 + lr + ((r >= 2) ? 8 : 0);
                int po = nq * 32 + nt * 8 + lc * 2 + (r & 1);
                float y = fmaxf(fmaxf(acc1[mt][nt][r] + bc, 0.f) + acc2[mt][nt][r] + bd, 0.f);
                sO[po * 68 + oo] = y;
            }
        }
    }
    __syncthreads();
#pragma unroll
    for (int gi = 0; gi < 4; gi++) {
        for (int idx = tid; idx < 480; idx += 256) {
            int t = idx >> 4, q = idx & 15;
            float4 v = *(float4*)&sO[(gi * 32 + t) * 68 + q * 4];
            __half2 h0 = __floats2half2_rn(v.x, v.y);
            __half2 h1 = __floats2half2_rn(v.z, v.w);
            uint2 u;
            u.x = *(uint32_t*)&h0; u.y = *(uint32_t*)&h1;
            *(uint2*)(g_X1h + (size_t)((g0 + gi) * 30 + t) * 128 + m0 + q * 4) = u;
        }
    }
}

// ---------------- fp16 mma TCN block: 3-stage cp.async ring + ldmatrix ----------------
// (round-9 configuration: 4 graphs/CTA, occ 2)
// OUTM: 1 = fp16 [pos][C]; 2 = fp16 transposed [g][c*30+t]
template <int CIN, int COUT, int DIL, int NCH, int OUTM>
__global__ __launch_bounds__(256, 2) void k_tcnH(
    const __half* __restrict__ Xin, const __half* __restrict__ wC,
    const __half* __restrict__ wD, const float* __restrict__ cb,
    const float* __restrict__ db, __half* __restrict__ Xout) {
    constexpr int W = 32 + 2 * DIL;
    constexpr int BB = 4 * W * 40;
    constexpr int AB = 64 * 104;
    constexpr int DB = 64 * 40;
    constexpr int STG = BB + AB + DB;
    extern __shared__ __half smh[];
    const uint32_t smem0 = (uint32_t)__cvta_generic_to_shared(smh);

    const int tid = threadIdx.x;
    const int wrp = tid >> 5, lane = tid & 31;
    const int lr = lane >> 2, lc = lane & 3;
    const int l8 = lane & 7, s1 = (lane >> 3) & 1, s2 = lane >> 4;
    const int mh = wrp & 1;
    const int nq = wrp >> 1;
    const int mb = blockIdx.x;
    const int m0 = mb * 64;
    const int g0 = blockIdx.y * 4;

    {
        constexpr int ZR = 2 * DIL + 2;
        uint4 z = make_uint4(0, 0, 0, 0);
        for (int idx = tid; idx < 3 * 4 * ZR * 5; idx += 256) {
            int bufg = idx / (ZR * 5);
            int r = idx - bufg * (ZR * 5);
            int zr = r / 5, pc = r - (r / 5) * 5;
            int u = (zr < 2 * DIL) ? zr : (30 + zr);
            int buf = bufg >> 2, gi = bufg & 3;
            *(uint4*)(smh + buf * STG + (gi * W + u) * 40 + pc * 8) = z;
        }
    }

    auto stage = [&](int chk, int buf) {
        uint32_t sb = smem0 + buf * (STG * 2);
        for (int idx = tid; idx < 480; idx += 256) {
            int gi = idx / 120;
            int r = idx - gi * 120;
            int t = r >> 2, pc = r & 3;
            uint32_t dst = sb + (gi * W + t + 2 * DIL) * 80 + pc * 16;
            const __half* src = Xin + ((size_t)(g0 + gi) * 30 + t) * CIN + chk * 32 + pc * 8;
            CP16(dst, src);
        }
        uint32_t aD = sb + BB * 2;
        const __half* srcA = wC + ((size_t)(mb * NCH + chk) * 64) * 96;
        for (int idx = tid; idx < 768; idx += 256) {
            int o = idx / 12, pc = idx - (idx / 12) * 12;
            CP16(aD + o * 208 + pc * 16, srcA + o * 96 + pc * 8);
        }
        uint32_t dD = sb + (BB + AB) * 2;
        const __half* srcD = wD + ((size_t)(mb * NCH + chk) * 64) * 32;
        {
            int o = tid >> 2, pc = tid & 3;
            CP16(dD + o * 80 + pc * 16, srcD + o * 32 + pc * 8);
        }
        CP_COMMIT();
    };

    float acc1[2][4][4], acc2[2][4][4];
#pragma unroll
    for (int mt = 0; mt < 2; mt++)
#pragma unroll
        for (int nt = 0; nt < 4; nt++)
#pragma unroll
            for (int r = 0; r < 4; r++) { acc1[mt][nt][r] = 0.f; acc2[mt][nt][r] = 0.f; }

    stage(0, 0);
    stage(1, 1);

    for (int chk = 0; chk < NCH; chk++) {
        const int buf = chk % 3;
        if (chk + 1 < NCH) { CP_WAIT1(); } else { CP_WAIT0(); }
        __syncthreads();
        if (chk + 2 < NCH) stage(chk + 2, (chk + 2) % 3);

        const uint32_t sb = smem0 + buf * (STG * 2);
        const uint32_t bRow = sb + nq * (W * 80);
        const uint32_t aB = sb + BB * 2;
        const uint32_t dB = sb + (BB + AB) * 2;

#pragma unroll
        for (int kh = 0; kh < 2; kh++) {
            const uint32_t kb = kh * 32;
#pragma unroll
            for (int tap = 0; tap < 3; tap++) {
                uint32_t bf[4][2];
#pragma unroll
                for (int pr = 0; pr < 2; pr++) {
                    uint32_t ba = bRow +
                        (tap * DIL + (pr * 2 + s2) * 8 + l8) * 80 + kb + s1 * 16;
                    LDMX4(bf[pr * 2][0], bf[pr * 2][1], bf[pr * 2 + 1][0], bf[pr * 2 + 1][1], ba);
                }
                uint32_t af[2][4];
#pragma unroll
                for (int mt = 0; mt < 2; mt++) {
                    uint32_t aa = aB + (mh * 32 + mt * 16 + s1 * 8 + l8) * 208 +
                                  tap * 64 + kb + s2 * 16;
                    LDMX4(af[mt][0], af[mt][1], af[mt][2], af[mt][3], aa);
                }
#pragma unroll
                for (int mt = 0; mt < 2; mt++)
#pragma unroll
                    for (int nt = 0; nt < 4; nt++)
                        mma16(acc1[mt][nt], af[mt], bf[nt]);
                if (tap == 2) {
                    uint32_t df[2][4];
#pragma unroll
                    for (int mt = 0; mt < 2; mt++) {
                        uint32_t da = dB + (mh * 32 + mt * 16 + s1 * 8 + l8) * 80 +
                                      kb + s2 * 16;
                        LDMX4(df[mt][0], df[mt][1], df[mt][2], df[mt][3], da);
                    }
#pragma unroll
                    for (int mt = 0; mt < 2; mt++)
#pragma unroll
                        for (int nt = 0; nt < 4; nt++)
                            mma16(acc2[mt][nt], df[mt], bf[nt]);
                }
            }
        }
    }
    __syncthreads();

    float* sO = (float*)smh;
#pragma unroll
    for (int mt = 0; mt < 2; mt++) {
        int ob = m0 + mh * 32 + mt * 16 + lr;
        float bc0 = cb[ob], bc1 = cb[ob + 8];
        float bd0 = db[ob], bd1 = db[ob + 8];
#pragma unroll
        for (int nt = 0; nt < 4; nt++) {
#pragma unroll
            for (int r = 0; r < 4; r++) {
                float bc = (r >= 2) ? bc1 : bc0;
                float bd = (r >= 2) ? bd1 : bd0;
                int oo = mh * 32 + mt * 16 + lr + ((r >= 2) ? 8 : 0);
                int po = nq * 32 + nt * 8 + lc * 2 + (r & 1);
                float y = fmaxf(fmaxf(acc1[mt][nt][r] + bc, 0.f) + acc2[mt][nt][r] + bd, 0.f);
                sO[po * 68 + oo] = y;
            }
        }
    }
    __syncthreads();
    if (OUTM == 1) {
#pragma unroll
        for (int gi = 0; gi < 4; gi++) {
            for (int idx = tid; idx < 480; idx += 256) {
                int t = idx >> 4, q = idx & 15;
                float4 v = *(float4*)&sO[(gi * 32 + t) * 68 + q * 4];
                __half2 h0 = __floats2half2_rn(v.x, v.y);
                __half2 h1 = __floats2half2_rn(v.z, v.w);
                uint2 u;
                u.x = *(uint32_t*)&h0; u.y = *(uint32_t*)&h1;
                *(uint2*)(Xout + (size_t)((g0 + gi) * 30 + t) * COUT + m0 + q * 4) = u;
            }
        }
    } else {
#pragma unroll
        for (int gi = 0; gi < 4; gi++) {
            for (int idx = tid; idx < 960; idx += 256) {
                int c = idx / 15, th = idx - (idx / 15) * 15;
                int t = th * 2;
                float a = sO[(gi * 32 + t) * 68 + c];
                float b = sO[(gi * 32 + t + 1) * 68 + c];
                __half2 h = __floats2half2_rn(a, b);
                *(__half2*)(Xout + (size_t)(g0 + gi) * 3840 + (m0 + c) * 30 + t) = h;
            }
        }
    }
}

// ---------------- tensor-core FC: GF=32 graphs per CTA ----------------
#define FC_XST 40
#define FC_XBUF (32 * 40)
#define FC_WBUF (80 * 40)
#define FC_STRIDE (8 * FC_XBUF + 8 * FC_WBUF)
#define FC_SMEM (2 * FC_STRIDE * 2)

__global__ __launch_bounds__(256, 1) void k_fcM(
    const __half* __restrict__ X3T, const __half* __restrict__ fcwH,
    const float* __restrict__ fcb, float* __restrict__ out) {
    extern __shared__ __half sh[];
    const uint32_t s0 = (uint32_t)__cvta_generic_to_shared(sh);
    const int tid = threadIdx.x;
    const int wrp = tid >> 5, lane = tid & 31;
    const int l8 = lane & 7, s1 = (lane >> 3) & 1, s2 = lane >> 4;
    const int lr = lane >> 2, lc = lane & 3;
    const int g0 = blockIdx.x * 32;
    const int ks = wrp;

    auto stage = [&](int ch, int buf) {
        uint32_t base = s0 + buf * (FC_STRIDE * 2);
        for (int i = tid; i < 1024; i += 256) {
            int kss = i >> 7, r = i & 127;
            int g = r >> 2, q = r & 3;
            uint32_t dst = base + (kss * FC_XBUF + g * FC_XST) * 2 + q * 16;
            const __half* src = X3T + (size_t)(g0 + g) * 3840 + kss * 480 + ch * 32 + q * 8;
            CP16(dst, src);
        }
        for (int i = tid; i < 2560; i += 256) {
            int kss = i / 320, r = i - kss * 320;
            int j = r >> 2, q = r & 3;
            uint32_t dst = base + (8 * FC_XBUF + kss * FC_WBUF + j * FC_XST) * 2 + q * 16;
            const __half* src = fcwH + (size_t)(j < FCO ? j : 0) * 3840 + kss * 480 + ch * 32 + q * 8;
            if (j < FCO) CP16(dst, src); else CP16Z(dst, src);
        }
        CP_COMMIT();
    };

    float acc[2][10][4];
#pragma unroll
    for (int mt = 0; mt < 2; mt++)
#pragma unroll
        for (int nt = 0; nt < 10; nt++)
#pragma unroll
            for (int r = 0; r < 4; r++) acc[mt][nt][r] = 0.f;

    stage(0, 0);
    stage(1, 1);

    for (int ch = 0; ch < 15; ch++) {
        int buf = ch & 1;
        if (ch + 1 < 15) { CP_WAIT1(); } else { CP_WAIT0(); }
        __syncthreads();
        uint32_t xB = s0 + buf * (FC_STRIDE * 2) + ks * (FC_XBUF * 2);
        uint32_t wB = s0 + buf * (FC_STRIDE * 2) + (8 * FC_XBUF + ks * FC_WBUF) * 2;
#pragma unroll
        for (int k16 = 0; k16 < 2; k16++) {
            uint32_t kb = k16 * 32;
            uint32_t af[2][4];
#pragma unroll
            for (int mt = 0; mt < 2; mt++)
                LDMX4(af[mt][0], af[mt][1], af[mt][2], af[mt][3],
                      xB + (mt * 16 + s1 * 8 + l8) * 80 + kb + s2 * 16);
            uint32_t bf[10][2];
#pragma unroll
            for (int jt = 0; jt < 5; jt++) {
                LDMX4(bf[jt * 2][0], bf[jt * 2][1], bf[jt * 2 + 1][0], bf[jt * 2 + 1][1],
                      wB + (jt * 16 + s2 * 8 + l8) * 80 + kb + s1 * 16);
            }
#pragma unroll
            for (int mt = 0; mt < 2; mt++)
#pragma unroll
                for (int nt = 0; nt < 10; nt++) mma16(acc[mt][nt], af[mt], bf[nt]);
        }
        __syncthreads();
        if (ch + 2 < 15) stage(ch + 2, buf);
    }

    __syncthreads();
    float* sred = (float*)sh;   // [8][32][80]
#pragma unroll
    for (int mt = 0; mt < 2; mt++)
#pragma unroll
        for (int nt = 0; nt < 10; nt++)
#pragma unroll
            for (int r = 0; r < 4; r++) {
                int g = mt * 16 + lr + ((r & 2) ? 8 : 0);
                int j = nt * 8 + lc * 2 + (r & 1);
                sred[(ks * 32 + g) * 80 + j] = acc[mt][nt][r];
            }
    __syncthreads();
    for (int idx = tid; idx < 32 * FCO; idx += 256) {
        int g = idx / FCO, j = idx - (idx / FCO) * FCO;
        float s = 0.f;
#pragma unroll
        for (int w2 = 0; w2 < 8; w2++) s += sred[(w2 * 32 + g) * 80 + j];
        out[(size_t)(g0 + g) * FCO + j] = s + fcb[j];
    }
}

// ---------------- launch ----------------
extern "C" void kernel_launch(void* const* d_in, const int* in_sizes, int n_in,
                              void* d_out, int out_size) {
    const float* x    = (const float*)d_in[0];
    const void*  ei   = d_in[1];
    const float* gcnw = (const float*)d_in[2];
    const float* gcnb = (const float*)d_in[3];
    const float* cw0  = (const float*)d_in[4];
    const float* cb0  = (const float*)d_in[5];
    const float* dw0  = (const float*)d_in[6];
    const float* db0  = (const float*)d_in[7];
    const float* cw1  = (const float*)d_in[8];
    const float* cb1  = (const float*)d_in[9];
    const float* dw1  = (const float*)d_in[10];
    const float* db1  = (const float*)d_in[11];
    const float* cw2  = (const float*)d_in[12];
    const float* cb2  = (const float*)d_in[13];
    const float* dw2  = (const float*)d_in[14];
    const float* db2  = (const float*)d_in[15];
    const float* fcw  = (const float*)d_in[16];
    const float* fcb  = (const float*)d_in[17];
    float* out = (float*)d_out;

    void *pX1h, *pX2h, *pX3T, *pDeg, *pAcc;
    void *pWC0, *pWD0, *pWC1, *pWD1, *pWC2, *pWD2, *pFcwH;
    cudaGetSymbolAddress(&pX1h, g_X1h);
    cudaGetSymbolAddress(&pX2h, g_X2h);
    cudaGetSymbolAddress(&pX3T, g_X3T);
    cudaGetSymbolAddress(&pDeg, g_deg);
    cudaGetSymbolAddress(&pAcc, g_acc);
    cudaGetSymbolAddress(&pWC0, g_wC0);
    cudaGetSymbolAddress(&pWD0, g_wD0);
    cudaGetSymbolAddress(&pWC1, g_wC1);
    cudaGetSymbolAddress(&pWD1, g_wD1);
    cudaGetSymbolAddress(&pWC2, g_wC2);
    cudaGetSymbolAddress(&pWD2, g_wD2);
    cudaGetSymbolAddress(&pFcwH, g_fcwH);

    cudaMemsetAsync(pDeg, 0, NTOT * sizeof(float));
    cudaMemsetAsync(pAcc, 0, NTOT * 12 * sizeof(float));

    k_linDeg<<<2160, 256>>>(x, gcnw, ei);
    k_scatterW<<<5080, 256>>>(ei, cw0, dw0, cw1, dw1, cw2, dw2, fcw);

    cudaFuncSetAttribute(k_tcn0M, cudaFuncAttributeMaxDynamicSharedMemorySize, SM0_BYTES);
    k_tcn0M<<<dim3(2, NB / 4), 256, SM0_BYTES>>>(
        (const __half*)pWC0, (const __half*)pWD0, cb0, db0, gcnb);

    constexpr int SM1 = 3 * (4 * 38 * 40 + 64 * 104 + 64 * 40) * 2;
    constexpr int SM2 = 3 * (4 * 50 * 40 + 64 * 104 + 64 * 40) * 2;
    cudaFuncSetAttribute((const void*)k_tcnH<128, 512, 3, 4, 1>,
                         cudaFuncAttributeMaxDynamicSharedMemorySize, SM1);
    cudaFuncSetAttribute((const void*)k_tcnH<512, 128, 9, 16, 2>,
                         cudaFuncAttributeMaxDynamicSharedMemorySize, SM2);
    k_tcnH<128, 512, 3, 4, 1><<<dim3(8, NB / 4), 256, SM1>>>(
        (const __half*)pX1h, (const __half*)pWC1, (const __half*)pWD1, cb1, db1,
        (__half*)pX2h);
    k_tcnH<512, 128, 9, 16, 2><<<dim3(2, NB / 4), 256, SM2>>>(
        (const __half*)pX2h, (const __half*)pWC2, (const __half*)pWD2, cb2, db2,
        (__half*)pX3T);

    cudaFuncSetAttribute(k_fcM, cudaFuncAttributeMaxDynamicSharedMemorySize, FC_SMEM);
    k_fcM<<<NB / 32, 256, FC_SMEM>>>((const __half*)pX3T, (const __half*)pFcwH, fcb, out);
}